// round 4
// baseline (speedup 1.0000x reference)
#include <cuda_runtime.h>
#include <cuda_bf16.h>
#include <math_constants.h>

// NeighborsValuesAssigner: x(32,3,64,64), patches(2048,3,5,5), values(2048,128)
// out(32,128,64,64) fp32.
// dist = 0.5*||p||^2 - <p, window(x)>; top-8 smallest; out = mean values[idx].
//
// Pipeline:
//  1. prep:   bf16 patch matrix B[2048][80] = (-p | bias_hi | bias_lo | 0,0,0), fp32 bias
//  2. im2col: bf16 A[131072][80] = (window | 1 | 1 | 0,0,0)
//  3. gemm:   mma.sync bf16 distances + fused per-thread top-10 -> 40 cand/pos
//  4. rescue: exact fp32 distance on 40 candidates -> true top-8 indices
//  5. gather: mean of values rows

#define BB 32
#define CC 3
#define HW 64
#define NN 2048
#define DD 128
#define KNN 8
#define KVOL 75
#define KM 80                 // K padded for k16 MMA tiles
#define KM32 (KM / 2)         // 40 u32 per row
#define NPOS (BB * HW * HW)   // 131072
#define LL 10                 // per-thread candidate list length
#define NCAND 40              // 4 lanes * LL per position

__device__ float g_bias[NN];
__device__ unsigned g_pBu[NN * KM32];          // bf16x2 patch matrix
__device__ unsigned g_Au[NPOS * KM32];         // bf16x2 im2col matrix (21 MB)
__device__ int g_cand[NPOS * NCAND];           // candidate indices (21 MB)
__device__ int g_topk[NPOS * KNN];

// ---------------------------------------------------------------------------
// Kernel 1: patch prep — bias + negated bf16 rows with split-bias slots.
// ---------------------------------------------------------------------------
__global__ void prep_kernel(const float* __restrict__ patches) {
    int n = blockIdx.x * blockDim.x + threadIdx.x;
    if (n >= NN) return;
    const float* p = patches + n * KVOL;
    float s = 0.f;
    float pv[KM];
#pragma unroll
    for (int i = 0; i < KVOL; i++) {
        float v = p[i];
        s = fmaf(v, v, s);
        pv[i] = -v;
    }
    float bias = 0.5f * s;
    g_bias[n] = bias;
    float bh = __bfloat162float(__float2bfloat16_rn(bias));
    pv[75] = bias;          // placeholder, replaced by split below
    pv[75] = bh;
    pv[76] = bias - bh;     // low part (rounded to bf16 on store)
    pv[77] = 0.f; pv[78] = 0.f; pv[79] = 0.f;
    unsigned* dst = g_pBu + n * KM32;
#pragma unroll
    for (int k = 0; k < KM32; k++) {
        __nv_bfloat162 h2 = __floats2bfloat162_rn(pv[2 * k], pv[2 * k + 1]);
        dst[k] = *reinterpret_cast<unsigned*>(&h2);
    }
}

// ---------------------------------------------------------------------------
// Kernel 2: im2col — bf16 window rows, slots 75/76 = 1.0 (bias selectors).
// ---------------------------------------------------------------------------
__global__ void im2col_kernel(const float* __restrict__ x) {
    int pos = blockIdx.x * blockDim.x + threadIdx.x;
    if (pos >= NPOS) return;
    int w = pos & 63;
    int h = (pos >> 6) & 63;
    int b = pos >> 12;
    float xv[KM];
#pragma unroll
    for (int c = 0; c < CC; c++)
#pragma unroll
        for (int kh = 0; kh < 5; kh++) {
            int hy = h + kh - 2;
            bool rok = (hy >= 0) && (hy < HW);
            const float* xrow = x + ((b * CC + c) * HW + hy) * HW;
#pragma unroll
            for (int kw = 0; kw < 5; kw++) {
                int wx = w + kw - 2;
                float v = 0.f;
                if (rok && wx >= 0 && wx < HW) v = xrow[wx];
                xv[(c * 5 + kh) * 5 + kw] = v;
            }
        }
    xv[75] = 1.0f; xv[76] = 1.0f; xv[77] = 0.f; xv[78] = 0.f; xv[79] = 0.f;
    unsigned* dst = g_Au + (size_t)pos * KM32;
#pragma unroll
    for (int k = 0; k < KM32; k++) {
        __nv_bfloat162 h2 = __floats2bfloat162_rn(xv[2 * k], xv[2 * k + 1]);
        dst[k] = *reinterpret_cast<unsigned*>(&h2);
    }
}

// ---------------------------------------------------------------------------
// Kernel 3: bf16 mma.sync distance GEMM with fused per-thread top-10.
// CTA = 256 thr (8 warps), 128 positions; warp owns a 16-row m-tile and
// sweeps all 2048 patches in 16 smem-staged chunks of 128.
// ---------------------------------------------------------------------------
__device__ __forceinline__ void ladder10(float v, int idx, float* lv, int* li) {
    float c = v; int ci = idx;
#pragma unroll
    for (int j = 0; j < LL; j++) {
        float dj = lv[j]; int ij = li[j];
        bool lt = c < dj;
        lv[j] = lt ? c : dj;  li[j] = lt ? ci : ij;
        c = lt ? dj : c;      ci = lt ? ij : ci;
    }
}

__global__ void __launch_bounds__(256, 2)
gemm_topk_kernel() {
    __shared__ unsigned sB[128 * 44]; // patch chunk rows padded 40->44 u32

    int warp = threadIdx.x >> 5;
    int lane = threadIdx.x & 31;
    int rowbase = blockIdx.x * 128 + warp * 16;
    int r1 = rowbase + (lane >> 2);

    // A fragments for the warp's 16 rows, whole K=80 (5 k-tiles), kept in regs
    unsigned aR[5][4];
    {
        const unsigned* A1 = g_Au + (size_t)r1 * KM32;
        const unsigned* A2 = A1 + 8 * KM32;
#pragma unroll
        for (int kt = 0; kt < 5; kt++) {
            int o = kt * 8 + (lane & 3);
            aR[kt][0] = A1[o];
            aR[kt][1] = A2[o];
            aR[kt][2] = A1[o + 4];
            aR[kt][3] = A2[o + 4];
        }
    }

    float lv0[LL], lv1[LL];
    int li0[LL], li1[LL];
#pragma unroll
    for (int j = 0; j < LL; j++) {
        lv0[j] = 3.0e38f; li0[j] = 0;
        lv1[j] = 3.0e38f; li1[j] = 0;
    }

    for (int ch = 0; ch < 16; ch++) {
        __syncthreads();
        const unsigned* src = g_pBu + ch * 128 * KM32;
        for (int i = threadIdx.x; i < 128 * KM32; i += 256)
            sB[(i / KM32) * 44 + (i % KM32)] = src[i];
        __syncthreads();

#pragma unroll 4
        for (int nt = 0; nt < 16; nt++) {
            const unsigned* bp = &sB[(nt * 8 + (lane >> 2)) * 44 + (lane & 3)];
            float c0 = 0.f, c1 = 0.f, c2 = 0.f, c3 = 0.f;
#pragma unroll
            for (int kt = 0; kt < 5; kt++) {
                unsigned b0 = bp[kt * 8];
                unsigned b1 = bp[kt * 8 + 4];
                asm volatile(
                    "mma.sync.aligned.m16n8k16.row.col.f32.bf16.bf16.f32 "
                    "{%0,%1,%2,%3}, {%4,%5,%6,%7}, {%8,%9}, {%0,%1,%2,%3};"
                    : "+f"(c0), "+f"(c1), "+f"(c2), "+f"(c3)
                    : "r"(aR[kt][0]), "r"(aR[kt][1]), "r"(aR[kt][2]), "r"(aR[kt][3]),
                      "r"(b0), "r"(b1));
            }
            int pidx = ch * 128 + nt * 8 + (lane & 3) * 2;
            bool i0 = c0 < lv0[LL - 1];
            bool i1 = c1 < lv0[LL - 1];
            bool i2 = c2 < lv1[LL - 1];
            bool i3 = c3 < lv1[LL - 1];
            if (__any_sync(0xffffffffu, i0 | i1 | i2 | i3)) {
                ladder10(i0 ? c0 : CUDART_INF_F, pidx,     lv0, li0);
                ladder10(i1 ? c1 : CUDART_INF_F, pidx + 1, lv0, li0);
                ladder10(i2 ? c2 : CUDART_INF_F, pidx,     lv1, li1);
                ladder10(i3 ? c3 : CUDART_INF_F, pidx + 1, lv1, li1);
            }
        }
    }

    int col = (lane & 3) * LL;
    int* d0 = g_cand + (size_t)r1 * NCAND + col;
    int* d1 = g_cand + (size_t)(r1 + 8) * NCAND + col;
#pragma unroll
    for (int j = 0; j < LL; j++) { d0[j] = li0[j]; d1[j] = li1[j]; }
}

// ---------------------------------------------------------------------------
// Kernel 4: exact fp32 rescue — 1 warp per position, 40 candidates,
// top-8 via iterative __reduce_min_sync on order-preserving uint keys.
// ---------------------------------------------------------------------------
__device__ __forceinline__ unsigned okey(float f) {
    unsigned u = __float_as_uint(f);
    return (u & 0x80000000u) ? ~u : (u | 0x80000000u);
}

__global__ void __launch_bounds__(256)
rescue_kernel(const float* __restrict__ x, const float* __restrict__ patches) {
    __shared__ float sx[8][80];

    int warp = threadIdx.x >> 5;
    int lane = threadIdx.x & 31;
    int pos = blockIdx.x * 8 + warp;
    int w = pos & 63;
    int h = (pos >> 6) & 63;
    int b = pos >> 12;

    // stage the fp32 window
    for (int i = lane; i < KVOL; i += 32) {
        int c = i / 25;
        int r = (i % 25) / 5;
        int q = i % 5;
        int hy = h + r - 2;
        int wx = w + q - 2;
        float v = 0.f;
        if (hy >= 0 && hy < HW && wx >= 0 && wx < HW)
            v = x[((b * CC + c) * HW + hy) * HW + wx];
        sx[warp][i] = v;
    }
    __syncwarp();

    const int* cp = g_cand + (size_t)pos * NCAND;
    int idx1 = cp[lane];
    int idx2 = cp[32 + (lane & 7)]; // lanes >=8 mirror lane&7 (masked below)

    const float* p1 = patches + idx1 * KVOL;
    const float* p2 = patches + idx2 * KVOL;
    float a1 = 0.f, a2 = 0.f;
    const float* xw = sx[warp];
#pragma unroll 15
    for (int j = 0; j < KVOL; j++) {
        float xv = xw[j];
        a1 = fmaf(p1[j], xv, a1);
        a2 = fmaf(p2[j], xv, a2);
    }
    float d1 = g_bias[idx1] - a1;
    float d2 = g_bias[idx2] - a2;

    unsigned k1 = okey(d1);
    unsigned k2 = (lane < 8) ? okey(d2) : 0xFFFFFFFFu;

    int* outp = g_topk + (size_t)pos * KNN;
#pragma unroll
    for (int it = 0; it < KNN; it++) {
        unsigned mymin = min(k1, k2);
        unsigned m = __reduce_min_sync(0xffffffffu, mymin);
        bool own = (k1 == m) || (k2 == m);
        unsigned bal = __ballot_sync(0xffffffffu, own);
        int leader = __ffs(bal) - 1;
        if (lane == leader) {
            if (k1 == m) { outp[it] = idx1; k1 = 0xFFFFFFFFu; }
            else         { outp[it] = idx2; k2 = 0xFFFFFFFFu; }
        }
    }
}

// ---------------------------------------------------------------------------
// Kernel 5: gather + mean (coalesced via smem transpose).
// ---------------------------------------------------------------------------
__global__ void __launch_bounds__(256)
gather_kernel(const float* __restrict__ values, float* __restrict__ out) {
    __shared__ float ssum[32][133];

    int bh = blockIdx.x;
    int wt = blockIdx.y;
    int b = bh >> 6;
    int h = bh & 63;
    int w0 = wt * 32;

    int warp = threadIdx.x >> 5;
    int lane = threadIdx.x & 31;
    const float4* v4 = reinterpret_cast<const float4*>(values);

#pragma unroll
    for (int r = 0; r < 4; r++) {
        int pl = warp + r * 8;
        int pos = (bh * HW) + w0 + pl;
        const int* ip = g_topk + (size_t)pos * KNN;
        float4 a = make_float4(0.f, 0.f, 0.f, 0.f);
#pragma unroll
        for (int k = 0; k < KNN; k++) {
            int idx = ip[k];
            float4 v = v4[idx * (DD / 4) + lane];
            a.x += v.x; a.y += v.y; a.z += v.z; a.w += v.w;
        }
        ssum[pl][lane * 4 + 0] = a.x * 0.125f;
        ssum[pl][lane * 4 + 1] = a.y * 0.125f;
        ssum[pl][lane * 4 + 2] = a.z * 0.125f;
        ssum[pl][lane * 4 + 3] = a.w * 0.125f;
    }
    __syncthreads();

    int wl = threadIdx.x & 31;
    int d0 = threadIdx.x >> 5;
#pragma unroll
    for (int d = d0; d < DD; d += 8) {
        out[((b * DD + d) * HW + h) * HW + w0 + wl] = ssum[wl][d];
    }
}

// ---------------------------------------------------------------------------
extern "C" void kernel_launch(void* const* d_in, const int* in_sizes, int n_in,
                              void* d_out, int out_size) {
    const float* x = (const float*)d_in[0];
    const float* patches = (const float*)d_in[1];
    const float* values = (const float*)d_in[2];
    float* out = (float*)d_out;

    prep_kernel<<<(NN + 127) / 128, 128>>>(patches);
    im2col_kernel<<<NPOS / 256, 256>>>(x);
    gemm_topk_kernel<<<NPOS / 128, 256>>>();
    rescue_kernel<<<NPOS / 8, 256>>>(x, patches);
    gather_kernel<<<dim3(BB * HW, 2), 256>>>(values, out);
}

// round 5
// speedup vs baseline: 1.9972x; 1.9972x over previous
#include <cuda_runtime.h>
#include <cuda_bf16.h>

// NeighborsValuesAssigner: x(32,3,64,64), patches(2048,3,5,5), values(2048,128)
// out(32,128,64,64) fp32.
// dist = 0.5*||p||^2 - <p, window(x)>; top-8 smallest; out = mean values[idx].
//
// Pipeline:
//  1. prep:   bf16 patch matrix (negated, split-bias) + padded fp32 patch table
//  2. im2col: bf16 A[131072][80]
//  3. gemm:   mma.sync bf16 distances, fused per-lane top-10 of packed u32
//             keys (okey(dist)[31:11] | patch_idx) -> 40 candidates/position
//  4. rescue: exact fp32 distance on the 40 candidates (warp-cooperative,
//             LDG.128 rows) -> true top-8 indices
//  5. gather: mean of values rows

#define BB 32
#define CC 3
#define HW 64
#define NN 2048
#define DD 128
#define KNN 8
#define KVOL 75
#define KM 80                 // K padded for k16 MMA tiles
#define KM32 (KM / 2)         // 40 u32 per bf16x2 row
#define NPOS (BB * HW * HW)   // 131072
#define LL 10                 // per-lane candidate list length
#define NCAND 40              // 4 lanes * LL per position

__device__ float g_bias[NN];
__device__ float g_pf4[NN * 76];               // padded fp32 patch rows (16B-aligned)
__device__ unsigned g_pBu[NN * KM32];          // bf16x2 patch matrix
__device__ unsigned g_Au[NPOS * KM32];         // bf16x2 im2col matrix (21 MB)
__device__ unsigned g_cand[NPOS * NCAND];      // packed candidate keys (21 MB)
__device__ int g_topk[NPOS * KNN];

// order-preserving float->u32 key
__device__ __forceinline__ unsigned okey(float f) {
    unsigned u = __float_as_uint(f);
    int s = ((int)u) >> 31;
    return u ^ (unsigned)(s | 0x80000000);
}
// quantized key with 11-bit patch-index payload
__device__ __forceinline__ unsigned qkey(float f, unsigned pidx) {
    return (okey(f) & 0xFFFFF800u) | pidx;
}
// branchless sorted-insert (ascending, evict max): 2 ops per step
__device__ __forceinline__ void ins10(unsigned kv, unsigned* l) {
#pragma unroll
    for (int j = 0; j < LL; j++) {
        unsigned t = l[j];
        unsigned lo = min(kv, t);
        kv = max(kv, t);
        l[j] = lo;
    }
}

// ---------------------------------------------------------------------------
// Kernel 1: prep — bias, padded fp32 rows, negated bf16 rows w/ split bias.
// ---------------------------------------------------------------------------
__global__ void prep_kernel(const float* __restrict__ patches) {
    int n = blockIdx.x * blockDim.x + threadIdx.x;
    if (n >= NN) return;
    const float* p = patches + n * KVOL;
    float s = 0.f;
    float pv[KM];
    float* pf = g_pf4 + n * 76;
#pragma unroll
    for (int i = 0; i < KVOL; i++) {
        float v = p[i];
        s = fmaf(v, v, s);
        pv[i] = -v;
        pf[i] = v;
    }
    pf[75] = 0.f;
    float bias = 0.5f * s;
    g_bias[n] = bias;
    float bh = __bfloat162float(__float2bfloat16_rn(bias));
    pv[75] = bh;
    pv[76] = bias - bh;
    pv[77] = 0.f; pv[78] = 0.f; pv[79] = 0.f;
    unsigned* dst = g_pBu + n * KM32;
#pragma unroll
    for (int k = 0; k < KM32; k++) {
        __nv_bfloat162 h2 = __floats2bfloat162_rn(pv[2 * k], pv[2 * k + 1]);
        dst[k] = *reinterpret_cast<unsigned*>(&h2);
    }
}

// ---------------------------------------------------------------------------
// Kernel 2: im2col — bf16 window rows, slots 75/76 = 1.0 (bias selectors).
// ---------------------------------------------------------------------------
__global__ void im2col_kernel(const float* __restrict__ x) {
    int pos = blockIdx.x * blockDim.x + threadIdx.x;
    if (pos >= NPOS) return;
    int w = pos & 63;
    int h = (pos >> 6) & 63;
    int b = pos >> 12;
    float xv[KM];
#pragma unroll
    for (int c = 0; c < CC; c++)
#pragma unroll
        for (int kh = 0; kh < 5; kh++) {
            int hy = h + kh - 2;
            bool rok = (hy >= 0) && (hy < HW);
            const float* xrow = x + ((b * CC + c) * HW + hy) * HW;
#pragma unroll
            for (int kw = 0; kw < 5; kw++) {
                int wx = w + kw - 2;
                float v = 0.f;
                if (rok && wx >= 0 && wx < HW) v = xrow[wx];
                xv[(c * 5 + kh) * 5 + kw] = v;
            }
        }
    xv[75] = 1.0f; xv[76] = 1.0f; xv[77] = 0.f; xv[78] = 0.f; xv[79] = 0.f;
    unsigned* dst = g_Au + (size_t)pos * KM32;
#pragma unroll
    for (int k = 0; k < KM32; k++) {
        __nv_bfloat162 h2 = __floats2bfloat162_rn(xv[2 * k], xv[2 * k + 1]);
        dst[k] = *reinterpret_cast<unsigned*>(&h2);
    }
}

// ---------------------------------------------------------------------------
// Kernel 3: bf16 mma.sync distance GEMM + per-lane top-10 packed-key lists.
// smem B rows permuted so each B fragment pair is one LDS.64; stride 40 words
// is bank-conflict-free in both LDS.64 half-warp phases.
// ---------------------------------------------------------------------------
__global__ void __launch_bounds__(256, 2)
gemm_topk_kernel() {
    __shared__ unsigned sB[128 * KM32]; // 20 KB, permuted rows

    int warp = threadIdx.x >> 5;
    int lane = threadIdx.x & 31;
    int r1 = blockIdx.x * 128 + warp * 16 + (lane >> 2);

    // A fragments for the warp's 16 rows, whole K=80 (5 k-tiles)
    unsigned aR[5][4];
    {
        const unsigned* A1 = g_Au + (size_t)r1 * KM32;
        const unsigned* A2 = A1 + 8 * KM32;
#pragma unroll
        for (int kt = 0; kt < 5; kt++) {
            int o = kt * 8 + (lane & 3);
            aR[kt][0] = A1[o];
            aR[kt][1] = A2[o];
            aR[kt][2] = A1[o + 4];
            aR[kt][3] = A2[o + 4];
        }
    }

    unsigned lv0[LL], lv1[LL];
#pragma unroll
    for (int j = 0; j < LL; j++) { lv0[j] = 0xFFFFFFFFu; lv1[j] = 0xFFFFFFFFu; }

    for (int ch = 0; ch < 16; ch++) {
        __syncthreads();
        const unsigned* src = g_pBu + ch * 128 * KM32;
        for (int i = threadIdx.x; i < 128 * KM32; i += 256) {
            int n = i / KM32;
            int o = i - n * KM32;
            // permute: 8-group [w0..w7] -> [w0,w4,w1,w5,w2,w6,w3,w7]
            int p = (o & ~7) | ((o & 3) << 1) | ((o & 4) >> 2);
            sB[n * KM32 + p] = src[i];
        }
        __syncthreads();

#pragma unroll 4
        for (int nt = 0; nt < 16; nt++) {
            const uint2* bp = reinterpret_cast<const uint2*>(
                sB + (nt * 8 + (lane >> 2)) * KM32) + (lane & 3);
            float c0 = 0.f, c1 = 0.f, c2 = 0.f, c3 = 0.f;
#pragma unroll
            for (int kt = 0; kt < 5; kt++) {
                uint2 bb = bp[kt * 4]; // one LDS.64: orig words kt*8+c, kt*8+4+c
                asm volatile(
                    "mma.sync.aligned.m16n8k16.row.col.f32.bf16.bf16.f32 "
                    "{%0,%1,%2,%3}, {%4,%5,%6,%7}, {%8,%9}, {%0,%1,%2,%3};"
                    : "+f"(c0), "+f"(c1), "+f"(c2), "+f"(c3)
                    : "r"(aR[kt][0]), "r"(aR[kt][1]), "r"(aR[kt][2]), "r"(aR[kt][3]),
                      "r"(bb.x), "r"(bb.y));
            }
            unsigned pidx = ch * 128 + nt * 8 + (lane & 3) * 2;
            ins10(qkey(c0, pidx),     lv0);
            ins10(qkey(c1, pidx + 1), lv0);
            ins10(qkey(c2, pidx),     lv1);
            ins10(qkey(c3, pidx + 1), lv1);
        }
    }

    unsigned* d0 = g_cand + (size_t)r1 * NCAND + (lane & 3) * LL;
    unsigned* d1 = g_cand + (size_t)(r1 + 8) * NCAND + (lane & 3) * LL;
#pragma unroll
    for (int j = 0; j < LL; j++) { d0[j] = lv0[j]; d1[j] = lv1[j]; }
}

// ---------------------------------------------------------------------------
// Kernel 4: exact fp32 rescue — warp per position, candidate rows loaded as
// LDG.128 across 19 lanes, shfl-xor dot reduce, iterative min-extract top-8.
// ---------------------------------------------------------------------------
__global__ void __launch_bounds__(256)
rescue_kernel(const float* __restrict__ x) {
    int warp = threadIdx.x >> 5;
    int lane = threadIdx.x & 31;
    int pos = blockIdx.x * 8 + warp;
    int w = pos & 63;
    int h = (pos >> 6) & 63;
    int b = pos >> 12;

    // lane j (j<19) holds window elements 4j..4j+3 (element 75 -> 0)
    float x4[4] = {0.f, 0.f, 0.f, 0.f};
    if (lane < 19) {
#pragma unroll
        for (int t = 0; t < 4; t++) {
            int e = lane * 4 + t;
            if (e < KVOL) {
                int c = e / 25;
                int r = (e % 25) / 5;
                int q = e % 5;
                int hy = h + r - 2;
                int wx = w + q - 2;
                if (hy >= 0 && hy < HW && wx >= 0 && wx < HW)
                    x4[t] = x[((b * CC + c) * HW + hy) * HW + wx];
            }
        }
    }

    const unsigned* cp = g_cand + (size_t)pos * NCAND;
    unsigned v1 = cp[lane];
    unsigned v2 = cp[32 + (lane & 7)];

    unsigned k1 = 0xFFFFFFFFu, k2 = 0xFFFFFFFFu;
    int i1 = 0, i2 = 0;
    const float4* pf = reinterpret_cast<const float4*>(g_pf4);

    // candidates 0..31 (from v1)
#pragma unroll 4
    for (int c = 0; c < 32; c += 2) {
        int ia = (int)(__shfl_sync(0xffffffffu, v1, c) & 0x7FFu);
        int ib = (int)(__shfl_sync(0xffffffffu, v1, c + 1) & 0x7FFu);
        float sa = 0.f, sb = 0.f;
        if (lane < 19) {
            float4 pa = pf[ia * 19 + lane];
            float4 pb = pf[ib * 19 + lane];
            sa = fmaf(pa.x, x4[0], fmaf(pa.y, x4[1], fmaf(pa.z, x4[2], pa.w * x4[3])));
            sb = fmaf(pb.x, x4[0], fmaf(pb.y, x4[1], fmaf(pb.z, x4[2], pb.w * x4[3])));
        }
#pragma unroll
        for (int off = 16; off >= 1; off >>= 1) {
            sa += __shfl_xor_sync(0xffffffffu, sa, off);
            sb += __shfl_xor_sync(0xffffffffu, sb, off);
        }
        float da = g_bias[ia] - sa;
        float db = g_bias[ib] - sb;
        if (lane == c)     { k1 = okey(da); i1 = ia; }
        if (lane == c + 1) { k1 = okey(db); i1 = ib; }
    }
    // candidates 32..39 (from v2)
#pragma unroll
    for (int c = 0; c < 8; c += 2) {
        int ia = (int)(__shfl_sync(0xffffffffu, v2, c) & 0x7FFu);
        int ib = (int)(__shfl_sync(0xffffffffu, v2, c + 1) & 0x7FFu);
        float sa = 0.f, sb = 0.f;
        if (lane < 19) {
            float4 pa = pf[ia * 19 + lane];
            float4 pb = pf[ib * 19 + lane];
            sa = fmaf(pa.x, x4[0], fmaf(pa.y, x4[1], fmaf(pa.z, x4[2], pa.w * x4[3])));
            sb = fmaf(pb.x, x4[0], fmaf(pb.y, x4[1], fmaf(pb.z, x4[2], pb.w * x4[3])));
        }
#pragma unroll
        for (int off = 16; off >= 1; off >>= 1) {
            sa += __shfl_xor_sync(0xffffffffu, sa, off);
            sb += __shfl_xor_sync(0xffffffffu, sb, off);
        }
        float da = g_bias[ia] - sa;
        float db = g_bias[ib] - sb;
        if (lane == c)     { k2 = okey(da); i2 = ia; }
        if (lane == c + 1) { k2 = okey(db); i2 = ib; }
    }

    int* outp = g_topk + (size_t)pos * KNN;
#pragma unroll
    for (int it = 0; it < KNN; it++) {
        unsigned m = __reduce_min_sync(0xffffffffu, min(k1, k2));
        bool own = (k1 == m) || (k2 == m);
        unsigned bal = __ballot_sync(0xffffffffu, own);
        int leader = __ffs(bal) - 1;
        if (lane == leader) {
            if (k1 == m) { outp[it] = i1; k1 = 0xFFFFFFFFu; }
            else         { outp[it] = i2; k2 = 0xFFFFFFFFu; }
        }
    }
}

// ---------------------------------------------------------------------------
// Kernel 5: gather + mean (coalesced via smem transpose).
// ---------------------------------------------------------------------------
__global__ void __launch_bounds__(256)
gather_kernel(const float* __restrict__ values, float* __restrict__ out) {
    __shared__ float ssum[32][133];

    int bh = blockIdx.x;
    int wt = blockIdx.y;
    int b = bh >> 6;
    int h = bh & 63;
    int w0 = wt * 32;

    int warp = threadIdx.x >> 5;
    int lane = threadIdx.x & 31;
    const float4* v4 = reinterpret_cast<const float4*>(values);

#pragma unroll
    for (int r = 0; r < 4; r++) {
        int pl = warp + r * 8;
        int pos = (bh * HW) + w0 + pl;
        const int* ip = g_topk + (size_t)pos * KNN;
        float4 a = make_float4(0.f, 0.f, 0.f, 0.f);
#pragma unroll
        for (int k = 0; k < KNN; k++) {
            int idx = ip[k];
            float4 v = v4[idx * (DD / 4) + lane];
            a.x += v.x; a.y += v.y; a.z += v.z; a.w += v.w;
        }
        ssum[pl][lane * 4 + 0] = a.x * 0.125f;
        ssum[pl][lane * 4 + 1] = a.y * 0.125f;
        ssum[pl][lane * 4 + 2] = a.z * 0.125f;
        ssum[pl][lane * 4 + 3] = a.w * 0.125f;
    }
    __syncthreads();

    int wl = threadIdx.x & 31;
    int d0 = threadIdx.x >> 5;
#pragma unroll
    for (int d = d0; d < DD; d += 8) {
        out[((b * DD + d) * HW + h) * HW + w0 + wl] = ssum[wl][d];
    }
}

// ---------------------------------------------------------------------------
extern "C" void kernel_launch(void* const* d_in, const int* in_sizes, int n_in,
                              void* d_out, int out_size) {
    const float* x = (const float*)d_in[0];
    const float* patches = (const float*)d_in[1];
    const float* values = (const float*)d_in[2];
    float* out = (float*)d_out;

    prep_kernel<<<(NN + 127) / 128, 128>>>(patches);
    im2col_kernel<<<NPOS / 256, 256>>>(x);
    gemm_topk_kernel<<<NPOS / 128, 256>>>();
    rescue_kernel<<<NPOS / 8, 256>>>(x);
    gather_kernel<<<dim3(BB * HW, 2), 256>>>(values, out);
}

// round 7
// speedup vs baseline: 2.6138x; 1.3087x over previous
#include <cuda_runtime.h>
#include <cuda_bf16.h>

// NeighborsValuesAssigner: x(32,3,64,64), patches(2048,3,5,5), values(2048,128)
// out(32,128,64,64) fp32.
// dist = 0.5*||p||^2 - <p, window(x)>; top-8 smallest; out = mean values[idx].
//
// Pipeline:
//  1. prep:   bf16 patch matrix (negated, split bias) + fp32 patch table [96]
//  2. gemm:   fused im2col + mma.sync bf16 distances; per-lane top-10 of
//             packed u32 keys (okey(dist)[31:11] | patch_idx) maintained with
//             batched sort networks -> 40 candidates/position
//  3. rescue: exact fp32 distance on 40 candidates (8-lane groups, 4 at a
//             time, 3-shfl reduce) -> true top-8 indices
//  4. gather: mean of values rows

#define BB 32
#define CC 3
#define HW 64
#define NN 2048
#define DD 128
#define KNN 8
#define KVOL 75
#define KM 80                 // K padded for k16 MMA tiles
#define KM32 (KM / 2)         // 40 u32 per bf16x2 row
#define NPOS (BB * HW * HW)   // 131072
#define LL 10                 // per-lane candidate list length
#define NCAND 40              // 4 lanes * LL per position
#define PFW 96                // padded fp32 patch row (8 lanes x 12 floats)

__device__ float g_bias[NN];
__device__ float g_pf[NN * PFW];               // padded fp32 patch rows
__device__ unsigned g_pBu[NN * KM32];          // bf16x2 patch matrix
__device__ unsigned g_cand[NPOS * NCAND];      // packed candidate keys (21 MB)
__device__ int g_topk[NPOS * KNN];

// order-preserving float->u32 key (monotone for ALL floats incl. negatives)
__device__ __forceinline__ unsigned okey(float f) {
    unsigned u = __float_as_uint(f);
    int s = ((int)u) >> 31;
    return u ^ (unsigned)(s | 0x80000000);
}

// compare-exchange on u32
#define CEV(arr, a, b) { unsigned _lo = min(arr[a], arr[b]); \
                         arr[b] = max(arr[a], arr[b]); arr[a] = _lo; }

__device__ __forceinline__ void sort8(unsigned* v) {
    CEV(v,0,1) CEV(v,2,3) CEV(v,4,5) CEV(v,6,7)
    CEV(v,0,2) CEV(v,1,3) CEV(v,4,6) CEV(v,5,7)
    CEV(v,1,2) CEV(v,5,6) CEV(v,0,4) CEV(v,3,7)
    CEV(v,1,5) CEV(v,2,6)
    CEV(v,1,4) CEV(v,3,6)
    CEV(v,2,4) CEV(v,3,5)
    CEV(v,3,4)
}

__device__ __forceinline__ void sort10(unsigned* v) {
    CEV(v,4,9) CEV(v,3,8) CEV(v,2,7) CEV(v,1,6) CEV(v,0,5)
    CEV(v,1,4) CEV(v,6,9) CEV(v,0,3) CEV(v,5,8)
    CEV(v,0,2) CEV(v,3,6) CEV(v,7,9)
    CEV(v,0,1) CEV(v,2,4) CEV(v,5,7) CEV(v,8,9)
    CEV(v,1,2) CEV(v,4,6) CEV(v,7,8) CEV(v,3,5)
    CEV(v,2,5) CEV(v,6,8) CEV(v,1,3) CEV(v,4,7)
    CEV(v,2,3) CEV(v,6,7)
    CEV(v,3,4) CEV(v,5,6)
    CEV(v,4,5)
}

// L sorted asc(10), v sorted asc(8): L <- 10 smallest of union (then re-sort)
__device__ __forceinline__ void merge_batch(unsigned* L, unsigned* v) {
#pragma unroll
    for (int j = 2; j < LL; j++) L[j] = min(L[j], v[9 - j]);
    sort10(L);
}

// ---------------------------------------------------------------------------
// Kernel 1: prep — bias, padded fp32 rows, negated bf16 rows w/ split bias.
// ---------------------------------------------------------------------------
__global__ void prep_kernel(const float* __restrict__ patches) {
    int n = blockIdx.x * blockDim.x + threadIdx.x;
    if (n >= NN) return;
    const float* p = patches + n * KVOL;
    float s = 0.f;
    float pv[KM];
    float* pf = g_pf + n * PFW;
#pragma unroll
    for (int i = 0; i < KVOL; i++) {
        float v = p[i];
        s = fmaf(v, v, s);
        pv[i] = -v;
        pf[i] = v;
    }
#pragma unroll
    for (int i = KVOL; i < PFW; i++) pf[i] = 0.f;
    float bias = 0.5f * s;
    g_bias[n] = bias;
    float bh = __bfloat162float(__float2bfloat16_rn(bias));
    pv[75] = bh;
    pv[76] = bias - bh;
    pv[77] = 0.f; pv[78] = 0.f; pv[79] = 0.f;
    unsigned* dst = g_pBu + n * KM32;
#pragma unroll
    for (int k = 0; k < KM32; k++) {
        __nv_bfloat162 h2 = __floats2bfloat162_rn(pv[2 * k], pv[2 * k + 1]);
        dst[k] = *reinterpret_cast<unsigned*>(&h2);
    }
}

// ---------------------------------------------------------------------------
// Kernel 2: fused im2col + bf16 mma.sync GEMM + batched top-10 selection.
// Block = 128 positions (2 h-rows x 64 w). x tile staged in smem, A fragments
// built in registers. B chunk staged permuted for LDS.64 fragment loads.
// ---------------------------------------------------------------------------
__global__ void __launch_bounds__(256, 2)
gemm_topk_kernel(const float* __restrict__ x) {
    __shared__ float sX[CC][6][68];     // rows h0-2..h0+3, w -2..65 (zero-pad)
    __shared__ unsigned sB[128 * KM32]; // 20 KB, permuted rows

    int tid = threadIdx.x;
    int warp = tid >> 5;
    int lane = tid & 31;
    int pos0 = blockIdx.x * 128;
    int b = pos0 >> 12;
    int h0 = (pos0 >> 6) & 63;

    // ---- stage x tile ----
    for (int i = tid; i < CC * 6 * 68; i += 256) {
        int c = i / (6 * 68);
        int rem = i - c * 6 * 68;
        int r = rem / 68;
        int wi = rem - r * 68;
        int hy = h0 - 2 + r;
        int wx = wi - 2;
        float v = 0.f;
        if (hy >= 0 && hy < HW && wx >= 0 && wx < HW)
            v = x[((b * CC + c) * HW + hy) * HW + wx];
        sX[c][r][wi] = v;
    }
    __syncthreads();

    // ---- build A fragments in registers ----
    int hh = warp >> 2;                  // 0/1: which h row
    int w1 = (warp & 3) * 16 + (lane >> 2);
    int cq = lane & 3;
    int r1 = pos0 + warp * 16 + (lane >> 2);

    unsigned aR[5][4];
#pragma unroll
    for (int kt = 0; kt < 5; kt++) {
        int eb = 16 * kt + 2 * cq;
        float f[2][4]; // [w1 / w1+8][e0,e1,e2,e3]
#pragma unroll
        for (int t = 0; t < 4; t++) {
            int e = eb + (t >> 1) * 8 + (t & 1); // e0,e1,e2,e3
            float va, vb;
            if (e >= 77) { va = 0.f; vb = 0.f; }
            else if (e >= 75) { va = 1.f; vb = 1.f; }
            else {
                int c = e / 25;
                int r = (e % 25) / 5;
                int q = e % 5;
                va = sX[c][hh + r][w1 + q];
                vb = sX[c][hh + r][w1 + 8 + q];
            }
            f[0][t] = va; f[1][t] = vb;
        }
        __nv_bfloat162 h2;
        h2 = __floats2bfloat162_rn(f[0][0], f[0][1]); aR[kt][0] = *(unsigned*)&h2;
        h2 = __floats2bfloat162_rn(f[1][0], f[1][1]); aR[kt][1] = *(unsigned*)&h2;
        h2 = __floats2bfloat162_rn(f[0][2], f[0][3]); aR[kt][2] = *(unsigned*)&h2;
        h2 = __floats2bfloat162_rn(f[1][2], f[1][3]); aR[kt][3] = *(unsigned*)&h2;
    }

    unsigned lv0[LL], lv1[LL];
#pragma unroll
    for (int j = 0; j < LL; j++) { lv0[j] = 0xFFFFFFFFu; lv1[j] = 0xFFFFFFFFu; }

    for (int ch = 0; ch < 16; ch++) {
        __syncthreads();
        const unsigned* src = g_pBu + ch * 128 * KM32;
        for (int i = tid; i < 128 * KM32; i += 256) {
            int n = i / KM32;
            int o = i - n * KM32;
            // permute: 8-group [w0..w7] -> [w0,w4,w1,w5,w2,w6,w3,w7]
            int p = (o & ~7) | ((o & 3) << 1) | ((o & 4) >> 2);
            sB[n * KM32 + p] = src[i];
        }
        __syncthreads();

#pragma unroll
        for (int ntg = 0; ntg < 4; ntg++) {
            unsigned v0[8], v1[8];
#pragma unroll
            for (int t = 0; t < 4; t++) {
                int nt = ntg * 4 + t;
                const uint2* bp = reinterpret_cast<const uint2*>(
                    sB + (nt * 8 + (lane >> 2)) * KM32) + cq;
                float c0 = 0.f, c1 = 0.f, c2 = 0.f, c3 = 0.f;
#pragma unroll
                for (int kt = 0; kt < 5; kt++) {
                    uint2 bb = bp[kt * 4];
                    asm volatile(
                        "mma.sync.aligned.m16n8k16.row.col.f32.bf16.bf16.f32 "
                        "{%0,%1,%2,%3}, {%4,%5,%6,%7}, {%8,%9}, {%0,%1,%2,%3};"
                        : "+f"(c0), "+f"(c1), "+f"(c2), "+f"(c3)
                        : "r"(aR[kt][0]), "r"(aR[kt][1]), "r"(aR[kt][2]), "r"(aR[kt][3]),
                          "r"(bb.x), "r"(bb.y));
                }
                unsigned pidx = ch * 128 + nt * 8 + cq * 2;
                // okey: monotone for negative distances too (round-6 bug fix)
                v0[2 * t]     = (okey(c0) & 0xFFFFF800u) | pidx;
                v0[2 * t + 1] = (okey(c1) & 0xFFFFF800u) | (pidx + 1);
                v1[2 * t]     = (okey(c2) & 0xFFFFF800u) | pidx;
                v1[2 * t + 1] = (okey(c3) & 0xFFFFF800u) | (pidx + 1);
            }
            sort8(v0); merge_batch(lv0, v0);
            sort8(v1); merge_batch(lv1, v1);
        }
    }

    unsigned* d0 = g_cand + (size_t)r1 * NCAND + cq * LL;
    unsigned* d1 = g_cand + (size_t)(r1 + 8) * NCAND + cq * LL;
#pragma unroll
    for (int j = 0; j < LL; j++) { d0[j] = lv0[j]; d1[j] = lv1[j]; }
}

// ---------------------------------------------------------------------------
// Kernel 3: exact fp32 rescue — warp per position, 4 groups of 8 lanes,
// 4 candidates per iteration, 3-shfl group reduce, min-extract top-8.
// ---------------------------------------------------------------------------
__global__ void __launch_bounds__(256)
rescue_kernel(const float* __restrict__ x) {
    int warp = threadIdx.x >> 5;
    int lane = threadIdx.x & 31;
    int grp = lane >> 3;      // 0..3
    int sub = lane & 7;       // 0..7
    int pos = blockIdx.x * 8 + warp;
    int w = pos & 63;
    int h = (pos >> 6) & 63;
    int b = pos >> 12;

    // lane holds window elements sub*12 .. sub*12+11 (>=75 -> 0)
    float xw[12];
#pragma unroll
    for (int t = 0; t < 12; t++) {
        int e = sub * 12 + t;
        float v = 0.f;
        if (e < KVOL) {
            int c = e / 25;
            int r = (e % 25) / 5;
            int q = e % 5;
            int hy = h + r - 2;
            int wx = w + q - 2;
            if (hy >= 0 && hy < HW && wx >= 0 && wx < HW)
                v = x[((b * CC + c) * HW + hy) * HW + wx];
        }
        xw[t] = v;
    }

    // candidate ids: group g owns candidates 10g..10g+9
    const unsigned* cp = g_cand + (size_t)pos * NCAND;
    unsigned cA = cp[grp * 10 + sub];           // cands 0..7 of the group
    unsigned cB = cp[grp * 10 + 8 + (sub & 1)]; // cands 8,9

    unsigned k1 = 0xFFFFFFFFu, k2 = 0xFFFFFFFFu;
    int i1 = 0, i2 = 0;
    const float4* pf = reinterpret_cast<const float4*>(g_pf);

#pragma unroll
    for (int c = 0; c < 10; c++) {
        unsigned kraw = (c < 8)
            ? __shfl_sync(0xffffffffu, cA, grp * 8 + c)
            : __shfl_sync(0xffffffffu, cB, grp * 8 + (c - 8));
        int idx = (int)(kraw & 0x7FFu);
        const float4* row = pf + idx * (PFW / 4) + sub * 3;
        float4 a = row[0], bq = row[1], cc = row[2];
        float s;
        s = fmaf(a.x,  xw[0],  a.y * xw[1]);
        s = fmaf(a.z,  xw[2],  s);
        s = fmaf(a.w,  xw[3],  s);
        s = fmaf(bq.x, xw[4],  s);
        s = fmaf(bq.y, xw[5],  s);
        s = fmaf(bq.z, xw[6],  s);
        s = fmaf(bq.w, xw[7],  s);
        s = fmaf(cc.x, xw[8],  s);
        s = fmaf(cc.y, xw[9],  s);
        s = fmaf(cc.z, xw[10], s);
        s = fmaf(cc.w, xw[11], s);
        // reduce within the 8-lane group (warp-wide shfl serves all 4 groups)
        s += __shfl_xor_sync(0xffffffffu, s, 4);
        s += __shfl_xor_sync(0xffffffffu, s, 2);
        s += __shfl_xor_sync(0xffffffffu, s, 1);
        float dist = g_bias[idx] - s;
        if (c < 8) {
            if (sub == c) { k1 = okey(dist); i1 = idx; }
        } else {
            if (sub == c - 8) { k2 = okey(dist); i2 = idx; }
        }
    }

    int* outp = g_topk + (size_t)pos * KNN;
#pragma unroll
    for (int it = 0; it < KNN; it++) {
        unsigned m = __reduce_min_sync(0xffffffffu, min(k1, k2));
        bool own = (k1 == m) || (k2 == m);
        unsigned bal = __ballot_sync(0xffffffffu, own);
        int leader = __ffs(bal) - 1;
        if (lane == leader) {
            if (k1 == m) { outp[it] = i1; k1 = 0xFFFFFFFFu; }
            else         { outp[it] = i2; k2 = 0xFFFFFFFFu; }
        }
    }
}

// ---------------------------------------------------------------------------
// Kernel 4: gather + mean (coalesced via smem transpose).
// ---------------------------------------------------------------------------
__global__ void __launch_bounds__(256)
gather_kernel(const float* __restrict__ values, float* __restrict__ out) {
    __shared__ float ssum[32][133];

    int bh = blockIdx.x;
    int wt = blockIdx.y;
    int b = bh >> 6;
    int h = bh & 63;
    int w0 = wt * 32;

    int warp = threadIdx.x >> 5;
    int lane = threadIdx.x & 31;
    const float4* v4 = reinterpret_cast<const float4*>(values);

#pragma unroll
    for (int r = 0; r < 4; r++) {
        int pl = warp + r * 8;
        int pos = (bh * HW) + w0 + pl;
        const int* ip = g_topk + (size_t)pos * KNN;
        float4 a = make_float4(0.f, 0.f, 0.f, 0.f);
#pragma unroll
        for (int k = 0; k < KNN; k++) {
            int idx = ip[k];
            float4 v = v4[idx * (DD / 4) + lane];
            a.x += v.x; a.y += v.y; a.z += v.z; a.w += v.w;
        }
        ssum[pl][lane * 4 + 0] = a.x * 0.125f;
        ssum[pl][lane * 4 + 1] = a.y * 0.125f;
        ssum[pl][lane * 4 + 2] = a.z * 0.125f;
        ssum[pl][lane * 4 + 3] = a.w * 0.125f;
    }
    __syncthreads();

    int wl = threadIdx.x & 31;
    int d0 = threadIdx.x >> 5;
#pragma unroll
    for (int d = d0; d < DD; d += 8) {
        out[((b * DD + d) * HW + h) * HW + w0 + wl] = ssum[wl][d];
    }
}

// ---------------------------------------------------------------------------
extern "C" void kernel_launch(void* const* d_in, const int* in_sizes, int n_in,
                              void* d_out, int out_size) {
    const float* x = (const float*)d_in[0];
    const float* patches = (const float*)d_in[1];
    const float* values = (const float*)d_in[2];
    float* out = (float*)d_out;

    prep_kernel<<<(NN + 127) / 128, 128>>>(patches);
    gemm_topk_kernel<<<NPOS / 128, 256>>>(x);
    rescue_kernel<<<NPOS / 8, 256>>>(x);
    gather_kernel<<<dim3(BB * HW, 2), 256>>>(values, out);
}

// round 8
// speedup vs baseline: 3.3440x; 1.2794x over previous
#include <cuda_runtime.h>
#include <cuda_bf16.h>

// NeighborsValuesAssigner: x(32,3,64,64), patches(2048,3,5,5), values(2048,128)
// out(32,128,64,64) fp32.
// dist = 0.5*||p||^2 - <p, window(x)>; top-8 smallest; out = mean values[idx].
//
// Pipeline:
//  1. prep:   bf16 patch matrix (negated, split bias, PRE-PERMUTED for MMA
//             fragment loads) + fp32 patch table [96]
//  2. gemm:   fused im2col + mma.sync bf16 distances; per-lane top-8 of
//             packed u32 keys (okey(dist)[31:11] | patch_idx), batched
//             sort8 + bitonic merge -> 32 candidates/position
//  3. rescue: exact fp32 distance on 32 candidates (8-lane groups) ->
//             true top-8 indices
//  4. gather: mean of values rows

#define BB 32
#define CC 3
#define HW 64
#define NN 2048
#define DD 128
#define KNN 8
#define KVOL 75
#define KM 80                 // K padded for k16 MMA tiles
#define KM32 (KM / 2)         // 40 u32 per bf16x2 row
#define NPOS (BB * HW * HW)   // 131072
#define LL 8                  // per-lane candidate list length
#define NCAND 32              // 4 lanes * LL per position
#define PFW 96                // padded fp32 patch row (8 lanes x 12 floats)

__device__ float g_bias[NN];
__device__ float g_pf[NN * PFW];               // padded fp32 patch rows
__device__ unsigned g_pBu[NN * KM32];          // bf16x2 patch matrix (permuted)
__device__ unsigned g_cand[NPOS * NCAND];      // packed candidate keys (16.8 MB)
__device__ int g_topk[NPOS * KNN];

// order-preserving float->u32 key (monotone for ALL floats incl. negatives)
__device__ __forceinline__ unsigned okey(float f) {
    unsigned u = __float_as_uint(f);
    int s = ((int)u) >> 31;
    return u ^ (unsigned)(s | 0x80000000);
}

// compare-exchange on u32
#define CEV(arr, a, b) { unsigned _lo = min(arr[a], arr[b]); \
                         arr[b] = max(arr[a], arr[b]); arr[a] = _lo; }

__device__ __forceinline__ void sort8(unsigned* v) {
    CEV(v,0,1) CEV(v,2,3) CEV(v,4,5) CEV(v,6,7)
    CEV(v,0,2) CEV(v,1,3) CEV(v,4,6) CEV(v,5,7)
    CEV(v,1,2) CEV(v,5,6) CEV(v,0,4) CEV(v,3,7)
    CEV(v,1,5) CEV(v,2,6)
    CEV(v,1,4) CEV(v,3,6)
    CEV(v,2,4) CEV(v,3,5)
    CEV(v,3,4)
}

// L sorted asc(8), v sorted asc(8): L <- 8 smallest of union, sorted.
// min(asc, reversed-asc) is bitonic -> 12-CE bitonic merger re-sorts.
__device__ __forceinline__ void merge8(unsigned* L, unsigned* v) {
#pragma unroll
    for (int j = 0; j < LL; j++) L[j] = min(L[j], v[7 - j]);
    CEV(L,0,4) CEV(L,1,5) CEV(L,2,6) CEV(L,3,7)
    CEV(L,0,2) CEV(L,1,3) CEV(L,4,6) CEV(L,5,7)
    CEV(L,0,1) CEV(L,2,3) CEV(L,4,5) CEV(L,6,7)
}

// ---------------------------------------------------------------------------
// Kernel 1: prep — bias, padded fp32 rows, negated bf16 rows w/ split bias,
// written in the MMA-fragment permuted order (8-group [w0..w7] ->
// [w0,w4,w1,w5,w2,w6,w3,w7]) so GEMM staging is a straight copy.
// ---------------------------------------------------------------------------
__global__ void prep_kernel(const float* __restrict__ patches) {
    int n = blockIdx.x * blockDim.x + threadIdx.x;
    if (n >= NN) return;
    const float* p = patches + n * KVOL;
    float s = 0.f;
    float pv[KM];
    float* pf = g_pf + n * PFW;
#pragma unroll
    for (int i = 0; i < KVOL; i++) {
        float v = p[i];
        s = fmaf(v, v, s);
        pv[i] = -v;
        pf[i] = v;
    }
#pragma unroll
    for (int i = KVOL; i < PFW; i++) pf[i] = 0.f;
    float bias = 0.5f * s;
    g_bias[n] = bias;
    float bh = __bfloat162float(__float2bfloat16_rn(bias));
    pv[75] = bh;
    pv[76] = bias - bh;
    pv[77] = 0.f; pv[78] = 0.f; pv[79] = 0.f;
    unsigned* dst = g_pBu + n * KM32;
#pragma unroll
    for (int k = 0; k < KM32; k++) {
        __nv_bfloat162 h2 = __floats2bfloat162_rn(pv[2 * k], pv[2 * k + 1]);
        int pp = (k & ~7) | ((k & 3) << 1) | ((k & 4) >> 2);
        dst[pp] = *reinterpret_cast<unsigned*>(&h2);
    }
}

// ---------------------------------------------------------------------------
// Kernel 2: fused im2col + bf16 mma.sync GEMM + batched top-8 selection.
// Block = 128 positions (2 h-rows x 64 w). x tile staged in smem, A fragments
// built in registers. B chunk staged by plain uint4 copy (pre-permuted).
// ---------------------------------------------------------------------------
__global__ void __launch_bounds__(256, 2)
gemm_topk_kernel(const float* __restrict__ x) {
    __shared__ float sX[CC][6][68];     // rows h0-2..h0+3, w -2..65 (zero-pad)
    __shared__ unsigned sB[128 * KM32]; // 20 KB

    int tid = threadIdx.x;
    int warp = tid >> 5;
    int lane = tid & 31;
    int pos0 = blockIdx.x * 128;
    int b = pos0 >> 12;
    int h0 = (pos0 >> 6) & 63;

    // ---- stage x tile ----
    for (int i = tid; i < CC * 6 * 68; i += 256) {
        int c = i / (6 * 68);
        int rem = i - c * 6 * 68;
        int r = rem / 68;
        int wi = rem - r * 68;
        int hy = h0 - 2 + r;
        int wx = wi - 2;
        float v = 0.f;
        if (hy >= 0 && hy < HW && wx >= 0 && wx < HW)
            v = x[((b * CC + c) * HW + hy) * HW + wx];
        sX[c][r][wi] = v;
    }
    __syncthreads();

    // ---- build A fragments in registers ----
    int hh = warp >> 2;                  // 0/1: which h row
    int w1 = (warp & 3) * 16 + (lane >> 2);
    int cq = lane & 3;
    int r1 = pos0 + warp * 16 + (lane >> 2);

    unsigned aR[5][4];
#pragma unroll
    for (int kt = 0; kt < 5; kt++) {
        int eb = 16 * kt + 2 * cq;
        float f[2][4]; // [w1 / w1+8][e0,e1,e2,e3]
#pragma unroll
        for (int t = 0; t < 4; t++) {
            int e = eb + (t >> 1) * 8 + (t & 1);
            float va, vb;
            if (e >= 77) { va = 0.f; vb = 0.f; }
            else if (e >= 75) { va = 1.f; vb = 1.f; }
            else {
                int c = e / 25;
                int r = (e % 25) / 5;
                int q = e % 5;
                va = sX[c][hh + r][w1 + q];
                vb = sX[c][hh + r][w1 + 8 + q];
            }
            f[0][t] = va; f[1][t] = vb;
        }
        __nv_bfloat162 h2;
        h2 = __floats2bfloat162_rn(f[0][0], f[0][1]); aR[kt][0] = *(unsigned*)&h2;
        h2 = __floats2bfloat162_rn(f[1][0], f[1][1]); aR[kt][1] = *(unsigned*)&h2;
        h2 = __floats2bfloat162_rn(f[0][2], f[0][3]); aR[kt][2] = *(unsigned*)&h2;
        h2 = __floats2bfloat162_rn(f[1][2], f[1][3]); aR[kt][3] = *(unsigned*)&h2;
    }

    unsigned lv0[LL], lv1[LL];
#pragma unroll
    for (int j = 0; j < LL; j++) { lv0[j] = 0xFFFFFFFFu; lv1[j] = 0xFFFFFFFFu; }

    for (int ch = 0; ch < 16; ch++) {
        __syncthreads();
        // straight vectorized copy: layout already MMA-permuted
        const uint4* src4 = reinterpret_cast<const uint4*>(g_pBu + ch * 128 * KM32);
        uint4* dst4 = reinterpret_cast<uint4*>(sB);
#pragma unroll
        for (int t = 0; t < 5; t++)
            dst4[tid + t * 256] = src4[tid + t * 256];
        __syncthreads();

#pragma unroll
        for (int ntg = 0; ntg < 4; ntg++) {
            unsigned v0[8], v1[8];
#pragma unroll
            for (int t = 0; t < 4; t++) {
                int nt = ntg * 4 + t;
                const uint2* bp = reinterpret_cast<const uint2*>(
                    sB + (nt * 8 + (lane >> 2)) * KM32) + cq;
                float c0 = 0.f, c1 = 0.f, c2 = 0.f, c3 = 0.f;
#pragma unroll
                for (int kt = 0; kt < 5; kt++) {
                    uint2 bb = bp[kt * 4];
                    asm volatile(
                        "mma.sync.aligned.m16n8k16.row.col.f32.bf16.bf16.f32 "
                        "{%0,%1,%2,%3}, {%4,%5,%6,%7}, {%8,%9}, {%0,%1,%2,%3};"
                        : "+f"(c0), "+f"(c1), "+f"(c2), "+f"(c3)
                        : "r"(aR[kt][0]), "r"(aR[kt][1]), "r"(aR[kt][2]), "r"(aR[kt][3]),
                          "r"(bb.x), "r"(bb.y));
                }
                unsigned pidx = ch * 128 + nt * 8 + cq * 2;
                v0[2 * t]     = (okey(c0) & 0xFFFFF800u) | pidx;
                v0[2 * t + 1] = (okey(c1) & 0xFFFFF800u) | (pidx + 1);
                v1[2 * t]     = (okey(c2) & 0xFFFFF800u) | pidx;
                v1[2 * t + 1] = (okey(c3) & 0xFFFFF800u) | (pidx + 1);
            }
            sort8(v0); merge8(lv0, v0);
            sort8(v1); merge8(lv1, v1);
        }
    }

    unsigned* d0 = g_cand + (size_t)r1 * NCAND + cq * LL;
    unsigned* d1 = g_cand + (size_t)(r1 + 8) * NCAND + cq * LL;
#pragma unroll
    for (int j = 0; j < LL; j++) { d0[j] = lv0[j]; d1[j] = lv1[j]; }
}

// ---------------------------------------------------------------------------
// Kernel 3: exact fp32 rescue — warp per position, 4 groups of 8 lanes,
// 8 candidates per group, 3-shfl group reduce, min-extract top-8 of 32.
// ---------------------------------------------------------------------------
__global__ void __launch_bounds__(256)
rescue_kernel(const float* __restrict__ x) {
    int warp = threadIdx.x >> 5;
    int lane = threadIdx.x & 31;
    int grp = lane >> 3;      // 0..3
    int sub = lane & 7;       // 0..7
    int pos = blockIdx.x * 8 + warp;
    int w = pos & 63;
    int h = (pos >> 6) & 63;
    int b = pos >> 12;

    // lane holds window elements sub*12 .. sub*12+11 (>=75 -> 0)
    float xw[12];
#pragma unroll
    for (int t = 0; t < 12; t++) {
        int e = sub * 12 + t;
        float v = 0.f;
        if (e < KVOL) {
            int c = e / 25;
            int r = (e % 25) / 5;
            int q = e % 5;
            int hy = h + r - 2;
            int wx = w + q - 2;
            if (hy >= 0 && hy < HW && wx >= 0 && wx < HW)
                v = x[((b * CC + c) * HW + hy) * HW + wx];
        }
        xw[t] = v;
    }

    // group g owns candidates 8g..8g+7; lane sub holds candidate sub
    const unsigned* cp = g_cand + (size_t)pos * NCAND;
    unsigned cA = cp[grp * 8 + sub];

    unsigned k1 = 0xFFFFFFFFu;
    int i1 = 0;
    const float4* pf = reinterpret_cast<const float4*>(g_pf);

#pragma unroll
    for (int c = 0; c < 8; c++) {
        unsigned kraw = __shfl_sync(0xffffffffu, cA, grp * 8 + c);
        int idx = (int)(kraw & 0x7FFu);
        const float4* row = pf + idx * (PFW / 4) + sub * 3;
        float4 a = row[0], bq = row[1], cc = row[2];
        float s;
        s = fmaf(a.x,  xw[0],  a.y * xw[1]);
        s = fmaf(a.z,  xw[2],  s);
        s = fmaf(a.w,  xw[3],  s);
        s = fmaf(bq.x, xw[4],  s);
        s = fmaf(bq.y, xw[5],  s);
        s = fmaf(bq.z, xw[6],  s);
        s = fmaf(bq.w, xw[7],  s);
        s = fmaf(cc.x, xw[8],  s);
        s = fmaf(cc.y, xw[9],  s);
        s = fmaf(cc.z, xw[10], s);
        s = fmaf(cc.w, xw[11], s);
        // reduce within the 8-lane group (warp-wide shfl serves all 4 groups)
        s += __shfl_xor_sync(0xffffffffu, s, 4);
        s += __shfl_xor_sync(0xffffffffu, s, 2);
        s += __shfl_xor_sync(0xffffffffu, s, 1);
        float dist = g_bias[idx] - s;
        if (sub == c) { k1 = okey(dist); i1 = idx; }
    }

    int* outp = g_topk + (size_t)pos * KNN;
#pragma unroll
    for (int it = 0; it < KNN; it++) {
        unsigned m = __reduce_min_sync(0xffffffffu, k1);
        bool own = (k1 == m);
        unsigned bal = __ballot_sync(0xffffffffu, own);
        int leader = __ffs(bal) - 1;
        if (lane == leader) {
            outp[it] = i1;
            k1 = 0xFFFFFFFFu;
        }
    }
}

// ---------------------------------------------------------------------------
// Kernel 4: gather + mean (coalesced via smem transpose).
// ---------------------------------------------------------------------------
__global__ void __launch_bounds__(256)
gather_kernel(const float* __restrict__ values, float* __restrict__ out) {
    __shared__ float ssum[32][133];

    int bh = blockIdx.x;
    int wt = blockIdx.y;
    int b = bh >> 6;
    int h = bh & 63;
    int w0 = wt * 32;

    int warp = threadIdx.x >> 5;
    int lane = threadIdx.x & 31;
    const float4* v4 = reinterpret_cast<const float4*>(values);

#pragma unroll
    for (int r = 0; r < 4; r++) {
        int pl = warp + r * 8;
        int pos = (bh * HW) + w0 + pl;
        const int* ip = g_topk + (size_t)pos * KNN;
        float4 a = make_float4(0.f, 0.f, 0.f, 0.f);
#pragma unroll
        for (int k = 0; k < KNN; k++) {
            int idx = ip[k];
            float4 v = v4[idx * (DD / 4) + lane];
            a.x += v.x; a.y += v.y; a.z += v.z; a.w += v.w;
        }
        ssum[pl][lane * 4 + 0] = a.x * 0.125f;
        ssum[pl][lane * 4 + 1] = a.y * 0.125f;
        ssum[pl][lane * 4 + 2] = a.z * 0.125f;
        ssum[pl][lane * 4 + 3] = a.w * 0.125f;
    }
    __syncthreads();

    int wl = threadIdx.x & 31;
    int d0 = threadIdx.x >> 5;
#pragma unroll
    for (int d = d0; d < DD; d += 8) {
        out[((b * DD + d) * HW + h) * HW + w0 + wl] = ssum[wl][d];
    }
}

// ---------------------------------------------------------------------------
extern "C" void kernel_launch(void* const* d_in, const int* in_sizes, int n_in,
                              void* d_out, int out_size) {
    const float* x = (const float*)d_in[0];
    const float* patches = (const float*)d_in[1];
    const float* values = (const float*)d_in[2];
    float* out = (float*)d_out;

    prep_kernel<<<(NN + 127) / 128, 128>>>(patches);
    gemm_topk_kernel<<<NPOS / 128, 256>>>(x);
    rescue_kernel<<<NPOS / 8, 256>>>(x);
    gather_kernel<<<dim3(BB * HW, 2), 256>>>(values, out);
}

// round 9
// speedup vs baseline: 3.4176x; 1.0220x over previous
#include <cuda_runtime.h>
#include <cuda_bf16.h>
#include <math_constants.h>

// NeighborsValuesAssigner: x(32,3,64,64), patches(2048,3,5,5), values(2048,128)
// out(32,128,64,64) fp32.
// dist = 0.5*||p||^2 - <p, window(x)>; top-8 smallest; out = mean values[idx].
//
// Pipeline:
//  1. prep:   bf16 patch matrix (negated, split bias, MMA-permuted) + fp32 table
//  2. gemm:   fused im2col + bf16 mma.sync, M=32 per warp (two m16 tiles share
//             each B fragment); per-lane top-8 of FLOAT keys with the patch
//             index packed into the low 11 mantissa bits; batched sort8 +
//             bitonic merge -> 32 candidates/position
//  3. rescue: exact fp32 distance on 32 candidates -> true top-8 indices
//  4. gather: mean of values rows

#define BB 32
#define CC 3
#define HW 64
#define NN 2048
#define DD 128
#define KNN 8
#define KVOL 75
#define KM 80                 // K padded for k16 MMA tiles
#define KM32 (KM / 2)         // 40 u32 per bf16x2 row
#define NPOS (BB * HW * HW)   // 131072
#define LL 8                  // per-lane candidate list length
#define NCAND 32              // 4 lanes * LL per position
#define PFW 96                // padded fp32 patch row (8 lanes x 12 floats)

__device__ float g_bias[NN];
__device__ float g_pf[NN * PFW];               // padded fp32 patch rows
__device__ unsigned g_pBu[NN * KM32];          // bf16x2 patch matrix (permuted)
__device__ unsigned g_cand[NPOS * NCAND];      // packed candidate keys (16.8 MB)
__device__ int g_topk[NPOS * KNN];

// order-preserving float->u32 key (rescue only; exact ranking)
__device__ __forceinline__ unsigned okey(float f) {
    unsigned u = __float_as_uint(f);
    int s = ((int)u) >> 31;
    return u ^ (unsigned)(s | 0x80000000);
}

// GEMM key: distance float with low 11 mantissa bits replaced by patch index.
// One LOP3. Float compares (FMNMX) give the correct order incl. negatives;
// index-bit ties are resolved exactly by the rescue pass.
__device__ __forceinline__ float packkey(float c, unsigned pidx) {
    unsigned u = (__float_as_uint(c) & 0xFFFFF800u) | pidx;
    return __uint_as_float(u);
}

// float compare-exchange
#define FCEV(arr, a, b) { float _lo = fminf(arr[a], arr[b]); \
                          arr[b] = fmaxf(arr[a], arr[b]); arr[a] = _lo; }

__device__ __forceinline__ void sort8f(float* v) {
    FCEV(v,0,1) FCEV(v,2,3) FCEV(v,4,5) FCEV(v,6,7)
    FCEV(v,0,2) FCEV(v,1,3) FCEV(v,4,6) FCEV(v,5,7)
    FCEV(v,1,2) FCEV(v,5,6) FCEV(v,0,4) FCEV(v,3,7)
    FCEV(v,1,5) FCEV(v,2,6)
    FCEV(v,1,4) FCEV(v,3,6)
    FCEV(v,2,4) FCEV(v,3,5)
    FCEV(v,3,4)
}

// L sorted asc(8), v sorted asc(8): L <- 8 smallest of union, sorted.
// min(asc, reversed-asc) is bitonic -> 12-CE bitonic merger re-sorts.
__device__ __forceinline__ void merge8f(float* L, float* v) {
#pragma unroll
    for (int j = 0; j < LL; j++) L[j] = fminf(L[j], v[7 - j]);
    FCEV(L,0,4) FCEV(L,1,5) FCEV(L,2,6) FCEV(L,3,7)
    FCEV(L,0,2) FCEV(L,1,3) FCEV(L,4,6) FCEV(L,5,7)
    FCEV(L,0,1) FCEV(L,2,3) FCEV(L,4,5) FCEV(L,6,7)
}

// ---------------------------------------------------------------------------
// Kernel 1: prep — bias, padded fp32 rows, negated bf16 rows w/ split bias,
// written in the MMA-fragment permuted order so GEMM staging is a plain copy.
// ---------------------------------------------------------------------------
__global__ void prep_kernel(const float* __restrict__ patches) {
    int n = blockIdx.x * blockDim.x + threadIdx.x;
    if (n >= NN) return;
    const float* p = patches + n * KVOL;
    float s = 0.f;
    float pv[KM];
    float* pf = g_pf + n * PFW;
#pragma unroll
    for (int i = 0; i < KVOL; i++) {
        float v = p[i];
        s = fmaf(v, v, s);
        pv[i] = -v;
        pf[i] = v;
    }
#pragma unroll
    for (int i = KVOL; i < PFW; i++) pf[i] = 0.f;
    float bias = 0.5f * s;
    g_bias[n] = bias;
    float bh = __bfloat162float(__float2bfloat16_rn(bias));
    pv[75] = bh;
    pv[76] = bias - bh;
    pv[77] = 0.f; pv[78] = 0.f; pv[79] = 0.f;
    unsigned* dst = g_pBu + n * KM32;
#pragma unroll
    for (int k = 0; k < KM32; k++) {
        __nv_bfloat162 h2 = __floats2bfloat162_rn(pv[2 * k], pv[2 * k + 1]);
        int pp = (k & ~7) | ((k & 3) << 1) | ((k & 4) >> 2);
        dst[pp] = *reinterpret_cast<unsigned*>(&h2);
    }
}

// ---------------------------------------------------------------------------
// Kernel 2: fused im2col + bf16 mma.sync GEMM + batched top-8 selection.
// Block = 256 positions (4 h-rows x 64 w). Warp owns 32 positions = two m16
// A-tiles, so every B fragment LDS feeds 2 MMAs. Per-thread 4 candidate lists.
// ---------------------------------------------------------------------------
__global__ void __launch_bounds__(256, 2)
gemm_topk_kernel(const float* __restrict__ x) {
    __shared__ float sX[CC][8][68];     // rows h0-2..h0+5, w -2..65 (zero-pad)
    __shared__ unsigned sB[128 * KM32]; // 20 KB

    int tid = threadIdx.x;
    int warp = tid >> 5;
    int lane = tid & 31;
    int pos0 = blockIdx.x * 256;
    int b = pos0 >> 12;
    int h0 = (pos0 >> 6) & 63;          // multiple of 4

    // ---- stage x tile (4 output rows + halo) ----
    for (int i = tid; i < CC * 8 * 68; i += 256) {
        int c = i / (8 * 68);
        int rem = i - c * 8 * 68;
        int r = rem / 68;
        int wi = rem - r * 68;
        int hy = h0 - 2 + r;
        int wx = wi - 2;
        float v = 0.f;
        if (hy >= 0 && hy < HW && wx >= 0 && wx < HW)
            v = x[((b * CC + c) * HW + hy) * HW + wx];
        sX[c][r][wi] = v;
    }
    __syncthreads();

    // warp -> h row (hh) + 32-wide w segment
    int hh = warp >> 1;                     // 0..3
    int wseg = (warp & 1) * 32;
    int w1 = wseg + (lane >> 2);            // tile0 row w; +8,+16,+24 others
    int cq = lane & 3;
    int r1 = pos0 + hh * 64 + w1;           // global position of list 0

    // ---- A fragments: 5 k-tiles x (4 regs tile0 + 4 regs tile1) ----
    unsigned aR[5][8];
#pragma unroll
    for (int kt = 0; kt < 5; kt++) {
        int eb = 16 * kt + 2 * cq;
        float f[4][4]; // [w-offset 0/8/16/24][e0,e1,e2,e3]
#pragma unroll
        for (int t = 0; t < 4; t++) {
            int e = eb + (t >> 1) * 8 + (t & 1);
            if (e >= 77) {
#pragma unroll
                for (int o = 0; o < 4; o++) f[o][t] = 0.f;
            } else if (e >= 75) {
#pragma unroll
                for (int o = 0; o < 4; o++) f[o][t] = 1.f;
            } else {
                int c = e / 25;
                int r = (e % 25) / 5;
                int q = e % 5;
#pragma unroll
                for (int o = 0; o < 4; o++)
                    f[o][t] = sX[c][hh + r][w1 - wseg + o * 8 + q + wseg];
            }
        }
        __nv_bfloat162 h2;
        h2 = __floats2bfloat162_rn(f[0][0], f[0][1]); aR[kt][0] = *(unsigned*)&h2;
        h2 = __floats2bfloat162_rn(f[1][0], f[1][1]); aR[kt][1] = *(unsigned*)&h2;
        h2 = __floats2bfloat162_rn(f[0][2], f[0][3]); aR[kt][2] = *(unsigned*)&h2;
        h2 = __floats2bfloat162_rn(f[1][2], f[1][3]); aR[kt][3] = *(unsigned*)&h2;
        h2 = __floats2bfloat162_rn(f[2][0], f[2][1]); aR[kt][4] = *(unsigned*)&h2;
        h2 = __floats2bfloat162_rn(f[3][0], f[3][1]); aR[kt][5] = *(unsigned*)&h2;
        h2 = __floats2bfloat162_rn(f[2][2], f[2][3]); aR[kt][6] = *(unsigned*)&h2;
        h2 = __floats2bfloat162_rn(f[3][2], f[3][3]); aR[kt][7] = *(unsigned*)&h2;
    }

    float lv0[LL], lv1[LL], lv2[LL], lv3[LL];
#pragma unroll
    for (int j = 0; j < LL; j++) {
        lv0[j] = CUDART_INF_F; lv1[j] = CUDART_INF_F;
        lv2[j] = CUDART_INF_F; lv3[j] = CUDART_INF_F;
    }

    for (int ch = 0; ch < 16; ch++) {
        __syncthreads();
        // straight vectorized copy: layout already MMA-permuted
        const uint4* src4 = reinterpret_cast<const uint4*>(g_pBu + ch * 128 * KM32);
        uint4* dst4 = reinterpret_cast<uint4*>(sB);
#pragma unroll
        for (int t = 0; t < 5; t++)
            dst4[tid + t * 256] = src4[tid + t * 256];
        __syncthreads();

#pragma unroll
        for (int ntg = 0; ntg < 4; ntg++) {
            float v0[8], v1[8], v2[8], v3[8];
#pragma unroll
            for (int t = 0; t < 4; t++) {
                int nt = ntg * 4 + t;
                const uint2* bp = reinterpret_cast<const uint2*>(
                    sB + (nt * 8 + (lane >> 2)) * KM32) + cq;
                float c0 = 0.f, c1 = 0.f, c2 = 0.f, c3 = 0.f;
                float d0 = 0.f, d1 = 0.f, d2 = 0.f, d3 = 0.f;
#pragma unroll
                for (int kt = 0; kt < 5; kt++) {
                    uint2 bb = bp[kt * 4]; // one LDS.64, feeds both MMAs
                    asm volatile(
                        "mma.sync.aligned.m16n8k16.row.col.f32.bf16.bf16.f32 "
                        "{%0,%1,%2,%3}, {%4,%5,%6,%7}, {%8,%9}, {%0,%1,%2,%3};"
                        : "+f"(c0), "+f"(c1), "+f"(c2), "+f"(c3)
                        : "r"(aR[kt][0]), "r"(aR[kt][1]), "r"(aR[kt][2]), "r"(aR[kt][3]),
                          "r"(bb.x), "r"(bb.y));
                    asm volatile(
                        "mma.sync.aligned.m16n8k16.row.col.f32.bf16.bf16.f32 "
                        "{%0,%1,%2,%3}, {%4,%5,%6,%7}, {%8,%9}, {%0,%1,%2,%3};"
                        : "+f"(d0), "+f"(d1), "+f"(d2), "+f"(d3)
                        : "r"(aR[kt][4]), "r"(aR[kt][5]), "r"(aR[kt][6]), "r"(aR[kt][7]),
                          "r"(bb.x), "r"(bb.y));
                }
                unsigned pidx = ch * 128 + nt * 8 + cq * 2;
                v0[2 * t] = packkey(c0, pidx); v0[2 * t + 1] = packkey(c1, pidx + 1);
                v1[2 * t] = packkey(c2, pidx); v1[2 * t + 1] = packkey(c3, pidx + 1);
                v2[2 * t] = packkey(d0, pidx); v2[2 * t + 1] = packkey(d1, pidx + 1);
                v3[2 * t] = packkey(d2, pidx); v3[2 * t + 1] = packkey(d3, pidx + 1);
            }
            sort8f(v0); merge8f(lv0, v0);
            sort8f(v1); merge8f(lv1, v1);
            sort8f(v2); merge8f(lv2, v2);
            sort8f(v3); merge8f(lv3, v3);
        }
    }

    unsigned* c0p = g_cand + (size_t)r1 * NCAND + cq * LL;
    unsigned* c1p = g_cand + (size_t)(r1 + 8) * NCAND + cq * LL;
    unsigned* c2p = g_cand + (size_t)(r1 + 16) * NCAND + cq * LL;
    unsigned* c3p = g_cand + (size_t)(r1 + 24) * NCAND + cq * LL;
#pragma unroll
    for (int j = 0; j < LL; j++) {
        c0p[j] = __float_as_uint(lv0[j]);
        c1p[j] = __float_as_uint(lv1[j]);
        c2p[j] = __float_as_uint(lv2[j]);
        c3p[j] = __float_as_uint(lv3[j]);
    }
}

// ---------------------------------------------------------------------------
// Kernel 3: exact fp32 rescue — warp per position, 4 groups of 8 lanes,
// 8 candidates per group, 3-shfl group reduce, min-extract top-8 of 32.
// ---------------------------------------------------------------------------
__global__ void __launch_bounds__(256)
rescue_kernel(const float* __restrict__ x) {
    int warp = threadIdx.x >> 5;
    int lane = threadIdx.x & 31;
    int grp = lane >> 3;      // 0..3
    int sub = lane & 7;       // 0..7
    int pos = blockIdx.x * 8 + warp;
    int w = pos & 63;
    int h = (pos >> 6) & 63;
    int b = pos >> 12;

    // lane holds window elements sub*12 .. sub*12+11 (>=75 -> 0)
    float xw[12];
#pragma unroll
    for (int t = 0; t < 12; t++) {
        int e = sub * 12 + t;
        float v = 0.f;
        if (e < KVOL) {
            int c = e / 25;
            int r = (e % 25) / 5;
            int q = e % 5;
            int hy = h + r - 2;
            int wx = w + q - 2;
            if (hy >= 0 && hy < HW && wx >= 0 && wx < HW)
                v = x[((b * CC + c) * HW + hy) * HW + wx];
        }
        xw[t] = v;
    }

    // group g owns candidates 8g..8g+7; lane sub holds candidate sub
    const unsigned* cp = g_cand + (size_t)pos * NCAND;
    unsigned cA = cp[grp * 8 + sub];

    unsigned k1 = 0xFFFFFFFFu;
    int i1 = 0;
    const float4* pf = reinterpret_cast<const float4*>(g_pf);

#pragma unroll
    for (int c = 0; c < 8; c++) {
        unsigned kraw = __shfl_sync(0xffffffffu, cA, grp * 8 + c);
        int idx = (int)(kraw & 0x7FFu);
        const float4* row = pf + idx * (PFW / 4) + sub * 3;
        float4 a = row[0], bq = row[1], cc = row[2];
        float s;
        s = fmaf(a.x,  xw[0],  a.y * xw[1]);
        s = fmaf(a.z,  xw[2],  s);
        s = fmaf(a.w,  xw[3],  s);
        s = fmaf(bq.x, xw[4],  s);
        s = fmaf(bq.y, xw[5],  s);
        s = fmaf(bq.z, xw[6],  s);
        s = fmaf(bq.w, xw[7],  s);
        s = fmaf(cc.x, xw[8],  s);
        s = fmaf(cc.y, xw[9],  s);
        s = fmaf(cc.z, xw[10], s);
        s = fmaf(cc.w, xw[11], s);
        // reduce within the 8-lane group (warp-wide shfl serves all 4 groups)
        s += __shfl_xor_sync(0xffffffffu, s, 4);
        s += __shfl_xor_sync(0xffffffffu, s, 2);
        s += __shfl_xor_sync(0xffffffffu, s, 1);
        float dist = g_bias[idx] - s;
        if (sub == c) { k1 = okey(dist); i1 = idx; }
    }

    int* outp = g_topk + (size_t)pos * KNN;
#pragma unroll
    for (int it = 0; it < KNN; it++) {
        unsigned m = __reduce_min_sync(0xffffffffu, k1);
        bool own = (k1 == m);
        unsigned bal = __ballot_sync(0xffffffffu, own);
        int leader = __ffs(bal) - 1;
        if (lane == leader) {
            outp[it] = i1;
            k1 = 0xFFFFFFFFu;
        }
    }
}

// ---------------------------------------------------------------------------
// Kernel 4: gather + mean (coalesced via smem transpose).
// ---------------------------------------------------------------------------
__global__ void __launch_bounds__(256)
gather_kernel(const float* __restrict__ values, float* __restrict__ out) {
    __shared__ float ssum[32][133];

    int bh = blockIdx.x;
    int wt = blockIdx.y;
    int b = bh >> 6;
    int h = bh & 63;
    int w0 = wt * 32;

    int warp = threadIdx.x >> 5;
    int lane = threadIdx.x & 31;
    const float4* v4 = reinterpret_cast<const float4*>(values);

#pragma unroll
    for (int r = 0; r < 4; r++) {
        int pl = warp + r * 8;
        int pos = (bh * HW) + w0 + pl;
        const int* ip = g_topk + (size_t)pos * KNN;
        float4 a = make_float4(0.f, 0.f, 0.f, 0.f);
#pragma unroll
        for (int k = 0; k < KNN; k++) {
            int idx = ip[k];
            float4 v = v4[idx * (DD / 4) + lane];
            a.x += v.x; a.y += v.y; a.z += v.z; a.w += v.w;
        }
        ssum[pl][lane * 4 + 0] = a.x * 0.125f;
        ssum[pl][lane * 4 + 1] = a.y * 0.125f;
        ssum[pl][lane * 4 + 2] = a.z * 0.125f;
        ssum[pl][lane * 4 + 3] = a.w * 0.125f;
    }
    __syncthreads();

    int wl = threadIdx.x & 31;
    int d0 = threadIdx.x >> 5;
#pragma unroll
    for (int d = d0; d < DD; d += 8) {
        out[((b * DD + d) * HW + h) * HW + w0 + wl] = ssum[wl][d];
    }
}

// ---------------------------------------------------------------------------
extern "C" void kernel_launch(void* const* d_in, const int* in_sizes, int n_in,
                              void* d_out, int out_size) {
    const float* x = (const float*)d_in[0];
    const float* patches = (const float*)d_in[1];
    const float* values = (const float*)d_in[2];
    float* out = (float*)d_out;

    prep_kernel<<<(NN + 127) / 128, 128>>>(patches);
    gemm_topk_kernel<<<NPOS / 256, 256>>>(x);
    rescue_kernel<<<NPOS / 8, 256>>>(x);
    gather_kernel<<<dim3(BB * HW, 2), 256>>>(values, out);
}

// round 10
// speedup vs baseline: 3.7579x; 1.0996x over previous
#include <cuda_runtime.h>
#include <cuda_bf16.h>
#include <math_constants.h>

// NeighborsValuesAssigner: x(32,3,64,64), patches(2048,3,5,5), values(2048,128)
// out(32,128,64,64) fp32.
// dist = 0.5*||p||^2 - <p, window(x)>; top-8 smallest; out = mean values[idx].
//
// Pipeline:
//  1. prep:   bf16 patch matrix (negated, split bias, MMA-permuted) + fp32 table
//  2. gemm:   fused im2col + bf16 mma.sync, M=32 per warp, 128-thread blocks
//             (no register spills: launch_bounds(128,3) -> 170-reg budget);
//             per-lane top-8 of FLOAT keys (patch idx in low 11 mantissa bits),
//             batched sort8 + bitonic merge -> 32 candidates/position
//  3. rescue: exact fp32 distance on 32 candidates -> true top-8 indices
//  4. gather: mean of values rows

#define BB 32
#define CC 3
#define HW 64
#define NN 2048
#define DD 128
#define KNN 8
#define KVOL 75
#define KM 80                 // K padded for k16 MMA tiles
#define KM32 (KM / 2)         // 40 u32 per bf16x2 row
#define NPOS (BB * HW * HW)   // 131072
#define LL 8                  // per-lane candidate list length
#define NCAND 32              // 4 lanes * LL per position
#define PFW 96                // padded fp32 patch row (8 lanes x 12 floats)

__device__ float g_bias[NN];
__device__ float g_pf[NN * PFW];               // padded fp32 patch rows
__device__ unsigned g_pBu[NN * KM32];          // bf16x2 patch matrix (permuted)
__device__ unsigned g_cand[NPOS * NCAND];      // packed candidate keys (16.8 MB)
__device__ int g_topk[NPOS * KNN];

// order-preserving float->u32 key (rescue only; exact ranking)
__device__ __forceinline__ unsigned okey(float f) {
    unsigned u = __float_as_uint(f);
    int s = ((int)u) >> 31;
    return u ^ (unsigned)(s | 0x80000000);
}

// GEMM key: distance float with low 11 mantissa bits replaced by patch index.
// One LOP3. Float compares (FMNMX) order correctly incl. negatives; index-bit
// ties are resolved exactly by the rescue pass.
__device__ __forceinline__ float packkey(float c, unsigned pidx) {
    unsigned u = (__float_as_uint(c) & 0xFFFFF800u) | pidx;
    return __uint_as_float(u);
}

// float compare-exchange
#define FCEV(arr, a, b) { float _lo = fminf(arr[a], arr[b]); \
                          arr[b] = fmaxf(arr[a], arr[b]); arr[a] = _lo; }

__device__ __forceinline__ void sort8f(float* v) {
    FCEV(v,0,1) FCEV(v,2,3) FCEV(v,4,5) FCEV(v,6,7)
    FCEV(v,0,2) FCEV(v,1,3) FCEV(v,4,6) FCEV(v,5,7)
    FCEV(v,1,2) FCEV(v,5,6) FCEV(v,0,4) FCEV(v,3,7)
    FCEV(v,1,5) FCEV(v,2,6)
    FCEV(v,1,4) FCEV(v,3,6)
    FCEV(v,2,4) FCEV(v,3,5)
    FCEV(v,3,4)
}

// L sorted asc(8), v sorted asc(8): L <- 8 smallest of union, sorted.
// min(asc, reversed-asc) is bitonic -> 12-CE bitonic merger re-sorts.
__device__ __forceinline__ void merge8f(float* L, float* v) {
#pragma unroll
    for (int j = 0; j < LL; j++) L[j] = fminf(L[j], v[7 - j]);
    FCEV(L,0,4) FCEV(L,1,5) FCEV(L,2,6) FCEV(L,3,7)
    FCEV(L,0,2) FCEV(L,1,3) FCEV(L,4,6) FCEV(L,5,7)
    FCEV(L,0,1) FCEV(L,2,3) FCEV(L,4,5) FCEV(L,6,7)
}

// ---------------------------------------------------------------------------
// Kernel 1: prep — bias, padded fp32 rows, negated bf16 rows w/ split bias,
// written in the MMA-fragment permuted order so GEMM staging is a plain copy.
// ---------------------------------------------------------------------------
__global__ void prep_kernel(const float* __restrict__ patches) {
    int n = blockIdx.x * blockDim.x + threadIdx.x;
    if (n >= NN) return;
    const float* p = patches + n * KVOL;
    float s = 0.f;
    float pv[KM];
    float* pf = g_pf + n * PFW;
#pragma unroll
    for (int i = 0; i < KVOL; i++) {
        float v = p[i];
        s = fmaf(v, v, s);
        pv[i] = -v;
        pf[i] = v;
    }
#pragma unroll
    for (int i = KVOL; i < PFW; i++) pf[i] = 0.f;
    float bias = 0.5f * s;
    g_bias[n] = bias;
    float bh = __bfloat162float(__float2bfloat16_rn(bias));
    pv[75] = bh;
    pv[76] = bias - bh;
    pv[77] = 0.f; pv[78] = 0.f; pv[79] = 0.f;
    unsigned* dst = g_pBu + n * KM32;
#pragma unroll
    for (int k = 0; k < KM32; k++) {
        __nv_bfloat162 h2 = __floats2bfloat162_rn(pv[2 * k], pv[2 * k + 1]);
        int pp = (k & ~7) | ((k & 3) << 1) | ((k & 4) >> 2);
        dst[pp] = *reinterpret_cast<unsigned*>(&h2);
    }
}

// ---------------------------------------------------------------------------
// Kernel 2: fused im2col + bf16 mma.sync GEMM + batched top-8 selection.
// Block = 128 threads = 4 warps; warp owns 32 positions (two m16 A-tiles that
// share every B fragment). 170-reg budget -> no spills; 12 warps/SM.
// ---------------------------------------------------------------------------
__global__ void __launch_bounds__(128, 3)
gemm_topk_kernel(const float* __restrict__ x) {
    __shared__ float sX[CC][6][68];     // rows h0-2..h0+3, w -2..65 (zero-pad)
    __shared__ unsigned sB[128 * KM32]; // 20 KB

    int tid = threadIdx.x;
    int warp = tid >> 5;
    int lane = tid & 31;
    int pos0 = blockIdx.x * 128;
    int b = pos0 >> 12;
    int h0 = (pos0 >> 6) & 63;          // multiple of 2

    // ---- stage x tile (2 output rows + halo) ----
    for (int i = tid; i < CC * 6 * 68; i += 128) {
        int c = i / (6 * 68);
        int rem = i - c * 6 * 68;
        int r = rem / 68;
        int wi = rem - r * 68;
        int hy = h0 - 2 + r;
        int wx = wi - 2;
        float v = 0.f;
        if (hy >= 0 && hy < HW && wx >= 0 && wx < HW)
            v = x[((b * CC + c) * HW + hy) * HW + wx];
        sX[c][r][wi] = v;
    }
    __syncthreads();

    // warp -> h row (hh) + 32-wide w segment
    int hh = warp >> 1;                     // 0..1
    int wseg = (warp & 1) * 32;
    int w1 = wseg + (lane >> 2);            // tile rows at w1, +8, +16, +24
    int cq = lane & 3;
    int r1 = pos0 + hh * 64 + w1;           // global position of list 0

    // ---- A fragments: 5 k-tiles x (4 regs tile0 + 4 regs tile1) ----
    unsigned aR[5][8];
#pragma unroll
    for (int kt = 0; kt < 5; kt++) {
        int eb = 16 * kt + 2 * cq;
        float f[4][4]; // [w-offset 0/8/16/24][e0,e1,e2,e3]
#pragma unroll
        for (int t = 0; t < 4; t++) {
            int e = eb + (t >> 1) * 8 + (t & 1);
            if (e >= 77) {
#pragma unroll
                for (int o = 0; o < 4; o++) f[o][t] = 0.f;
            } else if (e >= 75) {
#pragma unroll
                for (int o = 0; o < 4; o++) f[o][t] = 1.f;
            } else {
                int c = e / 25;
                int r = (e % 25) / 5;
                int q = e % 5;
#pragma unroll
                for (int o = 0; o < 4; o++)
                    f[o][t] = sX[c][hh + r][w1 + o * 8 + q];
            }
        }
        __nv_bfloat162 h2;
        h2 = __floats2bfloat162_rn(f[0][0], f[0][1]); aR[kt][0] = *(unsigned*)&h2;
        h2 = __floats2bfloat162_rn(f[1][0], f[1][1]); aR[kt][1] = *(unsigned*)&h2;
        h2 = __floats2bfloat162_rn(f[0][2], f[0][3]); aR[kt][2] = *(unsigned*)&h2;
        h2 = __floats2bfloat162_rn(f[1][2], f[1][3]); aR[kt][3] = *(unsigned*)&h2;
        h2 = __floats2bfloat162_rn(f[2][0], f[2][1]); aR[kt][4] = *(unsigned*)&h2;
        h2 = __floats2bfloat162_rn(f[3][0], f[3][1]); aR[kt][5] = *(unsigned*)&h2;
        h2 = __floats2bfloat162_rn(f[2][2], f[2][3]); aR[kt][6] = *(unsigned*)&h2;
        h2 = __floats2bfloat162_rn(f[3][2], f[3][3]); aR[kt][7] = *(unsigned*)&h2;
    }

    float lv0[LL], lv1[LL], lv2[LL], lv3[LL];
#pragma unroll
    for (int j = 0; j < LL; j++) {
        lv0[j] = CUDART_INF_F; lv1[j] = CUDART_INF_F;
        lv2[j] = CUDART_INF_F; lv3[j] = CUDART_INF_F;
    }

    for (int ch = 0; ch < 16; ch++) {
        __syncthreads();
        // straight vectorized copy: layout already MMA-permuted
        const uint4* src4 = reinterpret_cast<const uint4*>(g_pBu + ch * 128 * KM32);
        uint4* dst4 = reinterpret_cast<uint4*>(sB);
#pragma unroll
        for (int t = 0; t < 10; t++)
            dst4[tid + t * 128] = src4[tid + t * 128];
        __syncthreads();

#pragma unroll
        for (int ntg = 0; ntg < 4; ntg++) {
            float v0[8], v1[8], v2[8], v3[8];
#pragma unroll
            for (int t = 0; t < 4; t++) {
                int nt = ntg * 4 + t;
                const uint2* bp = reinterpret_cast<const uint2*>(
                    sB + (nt * 8 + (lane >> 2)) * KM32) + cq;
                float c0 = 0.f, c1 = 0.f, c2 = 0.f, c3 = 0.f;
                float d0 = 0.f, d1 = 0.f, d2 = 0.f, d3 = 0.f;
#pragma unroll
                for (int kt = 0; kt < 5; kt++) {
                    uint2 bb = bp[kt * 4]; // one LDS.64, feeds both MMAs
                    asm volatile(
                        "mma.sync.aligned.m16n8k16.row.col.f32.bf16.bf16.f32 "
                        "{%0,%1,%2,%3}, {%4,%5,%6,%7}, {%8,%9}, {%0,%1,%2,%3};"
                        : "+f"(c0), "+f"(c1), "+f"(c2), "+f"(c3)
                        : "r"(aR[kt][0]), "r"(aR[kt][1]), "r"(aR[kt][2]), "r"(aR[kt][3]),
                          "r"(bb.x), "r"(bb.y));
                    asm volatile(
                        "mma.sync.aligned.m16n8k16.row.col.f32.bf16.bf16.f32 "
                        "{%0,%1,%2,%3}, {%4,%5,%6,%7}, {%8,%9}, {%0,%1,%2,%3};"
                        : "+f"(d0), "+f"(d1), "+f"(d2), "+f"(d3)
                        : "r"(aR[kt][4]), "r"(aR[kt][5]), "r"(aR[kt][6]), "r"(aR[kt][7]),
                          "r"(bb.x), "r"(bb.y));
                }
                unsigned pidx = ch * 128 + nt * 8 + cq * 2;
                v0[2 * t] = packkey(c0, pidx); v0[2 * t + 1] = packkey(c1, pidx + 1);
                v1[2 * t] = packkey(c2, pidx); v1[2 * t + 1] = packkey(c3, pidx + 1);
                v2[2 * t] = packkey(d0, pidx); v2[2 * t + 1] = packkey(d1, pidx + 1);
                v3[2 * t] = packkey(d2, pidx); v3[2 * t + 1] = packkey(d3, pidx + 1);
            }
            sort8f(v0); merge8f(lv0, v0);
            sort8f(v1); merge8f(lv1, v1);
            sort8f(v2); merge8f(lv2, v2);
            sort8f(v3); merge8f(lv3, v3);
        }
    }

    unsigned* c0p = g_cand + (size_t)r1 * NCAND + cq * LL;
    unsigned* c1p = g_cand + (size_t)(r1 + 8) * NCAND + cq * LL;
    unsigned* c2p = g_cand + (size_t)(r1 + 16) * NCAND + cq * LL;
    unsigned* c3p = g_cand + (size_t)(r1 + 24) * NCAND + cq * LL;
#pragma unroll
    for (int j = 0; j < LL; j++) {
        c0p[j] = __float_as_uint(lv0[j]);
        c1p[j] = __float_as_uint(lv1[j]);
        c2p[j] = __float_as_uint(lv2[j]);
        c3p[j] = __float_as_uint(lv3[j]);
    }
}

// ---------------------------------------------------------------------------
// Kernel 3: exact fp32 rescue — warp per position, 4 groups of 8 lanes,
// 8 candidates per group, 3-shfl group reduce, min-extract top-8 of 32.
// ---------------------------------------------------------------------------
__global__ void __launch_bounds__(256)
rescue_kernel(const float* __restrict__ x) {
    int warp = threadIdx.x >> 5;
    int lane = threadIdx.x & 31;
    int grp = lane >> 3;      // 0..3
    int sub = lane & 7;       // 0..7
    int pos = blockIdx.x * 8 + warp;
    int w = pos & 63;
    int h = (pos >> 6) & 63;
    int b = pos >> 12;

    // lane holds window elements sub*12 .. sub*12+11 (>=75 -> 0)
    float xw[12];
#pragma unroll
    for (int t = 0; t < 12; t++) {
        int e = sub * 12 + t;
        float v = 0.f;
        if (e < KVOL) {
            int c = e / 25;
            int r = (e % 25) / 5;
            int q = e % 5;
            int hy = h + r - 2;
            int wx = w + q - 2;
            if (hy >= 0 && hy < HW && wx >= 0 && wx < HW)
                v = x[((b * CC + c) * HW + hy) * HW + wx];
        }
        xw[t] = v;
    }

    // group g owns candidates 8g..8g+7; lane sub holds candidate sub
    const unsigned* cp = g_cand + (size_t)pos * NCAND;
    unsigned cA = cp[grp * 8 + sub];

    unsigned k1 = 0xFFFFFFFFu;
    int i1 = 0;
    const float4* pf = reinterpret_cast<const float4*>(g_pf);

#pragma unroll
    for (int c = 0; c < 8; c++) {
        unsigned kraw = __shfl_sync(0xffffffffu, cA, grp * 8 + c);
        int idx = (int)(kraw & 0x7FFu);
        const float4* row = pf + idx * (PFW / 4) + sub * 3;
        float4 a = row[0], bq = row[1], cc = row[2];
        float s;
        s = fmaf(a.x,  xw[0],  a.y * xw[1]);
        s = fmaf(a.z,  xw[2],  s);
        s = fmaf(a.w,  xw[3],  s);
        s = fmaf(bq.x, xw[4],  s);
        s = fmaf(bq.y, xw[5],  s);
        s = fmaf(bq.z, xw[6],  s);
        s = fmaf(bq.w, xw[7],  s);
        s = fmaf(cc.x, xw[8],  s);
        s = fmaf(cc.y, xw[9],  s);
        s = fmaf(cc.z, xw[10], s);
        s = fmaf(cc.w, xw[11], s);
        // reduce within the 8-lane group (warp-wide shfl serves all 4 groups)
        s += __shfl_xor_sync(0xffffffffu, s, 4);
        s += __shfl_xor_sync(0xffffffffu, s, 2);
        s += __shfl_xor_sync(0xffffffffu, s, 1);
        float dist = g_bias[idx] - s;
        if (sub == c) { k1 = okey(dist); i1 = idx; }
    }

    int* outp = g_topk + (size_t)pos * KNN;
#pragma unroll
    for (int it = 0; it < KNN; it++) {
        unsigned m = __reduce_min_sync(0xffffffffu, k1);
        bool own = (k1 == m);
        unsigned bal = __ballot_sync(0xffffffffu, own);
        int leader = __ffs(bal) - 1;
        if (lane == leader) {
            outp[it] = i1;
            k1 = 0xFFFFFFFFu;
        }
    }
}

// ---------------------------------------------------------------------------
// Kernel 4: gather + mean (coalesced via smem transpose).
// ---------------------------------------------------------------------------
__global__ void __launch_bounds__(256)
gather_kernel(const float* __restrict__ values, float* __restrict__ out) {
    __shared__ float ssum[32][133];

    int bh = blockIdx.x;
    int wt = blockIdx.y;
    int b = bh >> 6;
    int h = bh & 63;
    int w0 = wt * 32;

    int warp = threadIdx.x >> 5;
    int lane = threadIdx.x & 31;
    const float4* v4 = reinterpret_cast<const float4*>(values);

#pragma unroll
    for (int r = 0; r < 4; r++) {
        int pl = warp + r * 8;
        int pos = (bh * HW) + w0 + pl;
        const int* ip = g_topk + (size_t)pos * KNN;
        float4 a = make_float4(0.f, 0.f, 0.f, 0.f);
#pragma unroll
        for (int k = 0; k < KNN; k++) {
            int idx = ip[k];
            float4 v = v4[idx * (DD / 4) + lane];
            a.x += v.x; a.y += v.y; a.z += v.z; a.w += v.w;
        }
        ssum[pl][lane * 4 + 0] = a.x * 0.125f;
        ssum[pl][lane * 4 + 1] = a.y * 0.125f;
        ssum[pl][lane * 4 + 2] = a.z * 0.125f;
        ssum[pl][lane * 4 + 3] = a.w * 0.125f;
    }
    __syncthreads();

    int wl = threadIdx.x & 31;
    int d0 = threadIdx.x >> 5;
#pragma unroll
    for (int d = d0; d < DD; d += 8) {
        out[((b * DD + d) * HW + h) * HW + w0 + wl] = ssum[wl][d];
    }
}

// ---------------------------------------------------------------------------
extern "C" void kernel_launch(void* const* d_in, const int* in_sizes, int n_in,
                              void* d_out, int out_size) {
    const float* x = (const float*)d_in[0];
    const float* patches = (const float*)d_in[1];
    const float* values = (const float*)d_in[2];
    float* out = (float*)d_out;

    prep_kernel<<<(NN + 127) / 128, 128>>>(patches);
    gemm_topk_kernel<<<NPOS / 128, 128>>>(x);
    rescue_kernel<<<NPOS / 8, 256>>>(x);
    gather_kernel<<<dim3(BB * HW, 2), 256>>>(values, out);
}